// round 12
// baseline (speedup 1.0000x reference)
#include <cuda_runtime.h>
#include <cstdint>

// Problem constants (fixed by the reference)
#define BB 16
#define NN 8192
#define MM 2048
#define KK 32
#define CC 128

// out layout: [pts (B*M*K*3 floats)] ++ [features (B*M*K*C floats)]
//
// R10 structure with ONE change: 64-thread CTAs (32 resident CTAs/SM, the
// HW slot limit). One CTA per (b, m), 2 warps:
//  - warp 0: normalized relative coords for all K=32 neighbors (lane = k)
//  - warp w copies rows {w, w+2, ..., w+30}: strict per-row
//    LDG.128 -> STG.128 interleave (every batching variant lost).
// More, smaller resident CTAs desynchronize the per-CTA startup bubbles,
// keeping the SM store stream dense (the one lever that measured positive:
// 8 CTAs/SM -> 16 CTAs/SM gave +0.5%).
__global__ __launch_bounds__(64, 32)
void knn_gather_norm_v11_kernel(const float* __restrict__ input,      // [B,N,C]
                                const float* __restrict__ points,     // [B,N,3]
                                const float* __restrict__ next_pts,   // [B,M,3]
                                const int*   __restrict__ indices,    // [B,M,K]
                                float* __restrict__ out_pts,          // [B,M,K,3]
                                float* __restrict__ out_feat)         // [B,M,K,C]
{
    const int bm = blockIdx.x;            // 0 .. B*M-1
    const int b  = bm / MM;

    __shared__ int sidx[KK];

    const int tid  = threadIdx.x;
    const int wid  = tid >> 5;
    const int lane = tid & 31;

    if (tid < KK) {
        sidx[tid] = indices[(size_t)bm * KK + tid];
    }
    __syncthreads();

    // ---- pts: warp 0, lane = neighbor k ----
    if (wid == 0) {
        const int k   = lane;
        const int idx = sidx[k];

        const float nx = __ldg(&next_pts[(size_t)bm * 3 + 0]);
        const float ny = __ldg(&next_pts[(size_t)bm * 3 + 1]);
        const float nz = __ldg(&next_pts[(size_t)bm * 3 + 2]);

        const float* p = points + ((size_t)b * NN + (size_t)idx) * 3;
        const float dx = __ldg(&p[0]) - nx;
        const float dy = __ldg(&p[1]) - ny;
        const float dz = __ldg(&p[2]) - nz;

        float mx = dx * dx + dy * dy + dz * dz;
        #pragma unroll
        for (int o = 16; o > 0; o >>= 1)
            mx = fmaxf(mx, __shfl_xor_sync(0xffffffffu, mx, o));

        float maxi = sqrtf(mx);
        if (maxi == 0.0f) maxi = 1.0f;
        const float inv = 1.0f / maxi;

        float* o = out_pts + ((size_t)bm * KK + (size_t)k) * 3;
        o[0] = dx * inv;
        o[1] = dy * inv;
        o[2] = dz * inv;
    }

    // ---- features: warp wid owns rows {wid, wid+2, ..., wid+30} ----
    #pragma unroll
    for (int k = wid; k < KK; k += 2) {
        const int idx = sidx[k];
        const float4* __restrict__ src =
            reinterpret_cast<const float4*>(input + ((size_t)b * NN + (size_t)idx) * CC);
        float4* __restrict__ dst =
            reinterpret_cast<float4*>(out_feat + ((size_t)bm * KK + (size_t)k) * CC);
        dst[lane] = src[lane];
    }
}

extern "C" void kernel_launch(void* const* d_in, const int* in_sizes, int n_in,
                              void* d_out, int out_size)
{
    const float* input    = (const float*)d_in[0];  // [B,N,C]
    const float* points   = (const float*)d_in[1];  // [B,N,3]
    const float* next_pts = (const float*)d_in[2];  // [B,M,3]
    const int*   indices  = (const int*)  d_in[3];  // [B,M,K]

    float* out_pts  = (float*)d_out;                         // B*M*K*3
    float* out_feat = out_pts + (size_t)BB * MM * KK * 3;    // B*M*K*C

    const int grid = BB * MM;   // 32768 CTAs
    knn_gather_norm_v11_kernel<<<grid, 64>>>(input, points, next_pts, indices,
                                             out_pts, out_feat);
}

// round 13
// speedup vs baseline: 1.0266x; 1.0266x over previous
#include <cuda_runtime.h>
#include <cstdint>

// Problem constants (fixed by the reference)
#define BB 16
#define NN 8192
#define MM 2048
#define KK 32
#define CC 128

// out layout: [pts (B*M*K*3 floats)] ++ [features (B*M*K*C floats)]
//
// R10 (best: 96.29us) with ONE change: warp w copies the 8 CONSECUTIVE
// rows {8w .. 8w+7} instead of the strided set {w, w+4, ...}. Each warp's
// store stream is now 4KB contiguous (successive 512B STG bursts hit the
// same/adjacent DRAM row), targeting write-stream efficiency.
// One CTA per (b, m), 128 threads = 4 warps, 16 resident CTAs/SM.
//  - warp 0: normalized relative coords for all K=32 neighbors (lane = k)
//  - strict per-row LDG.128 -> STG.128 interleave (batching variants lost).
__global__ __launch_bounds__(128, 16)
void knn_gather_norm_v12_kernel(const float* __restrict__ input,      // [B,N,C]
                                const float* __restrict__ points,     // [B,N,3]
                                const float* __restrict__ next_pts,   // [B,M,3]
                                const int*   __restrict__ indices,    // [B,M,K]
                                float* __restrict__ out_pts,          // [B,M,K,3]
                                float* __restrict__ out_feat)         // [B,M,K,C]
{
    const int bm = blockIdx.x;            // 0 .. B*M-1
    const int b  = bm / MM;

    __shared__ int sidx[KK];

    const int tid  = threadIdx.x;
    const int wid  = tid >> 5;
    const int lane = tid & 31;

    if (tid < KK) {
        sidx[tid] = indices[(size_t)bm * KK + tid];
    }
    __syncthreads();

    // ---- pts: warp 0, lane = neighbor k ----
    if (wid == 0) {
        const int k   = lane;
        const int idx = sidx[k];

        const float nx = __ldg(&next_pts[(size_t)bm * 3 + 0]);
        const float ny = __ldg(&next_pts[(size_t)bm * 3 + 1]);
        const float nz = __ldg(&next_pts[(size_t)bm * 3 + 2]);

        const float* p = points + ((size_t)b * NN + (size_t)idx) * 3;
        const float dx = __ldg(&p[0]) - nx;
        const float dy = __ldg(&p[1]) - ny;
        const float dz = __ldg(&p[2]) - nz;

        float mx = dx * dx + dy * dy + dz * dz;
        #pragma unroll
        for (int o = 16; o > 0; o >>= 1)
            mx = fmaxf(mx, __shfl_xor_sync(0xffffffffu, mx, o));

        float maxi = sqrtf(mx);
        if (maxi == 0.0f) maxi = 1.0f;
        const float inv = 1.0f / maxi;

        float* o = out_pts + ((size_t)bm * KK + (size_t)k) * 3;
        o[0] = dx * inv;
        o[1] = dy * inv;
        o[2] = dz * inv;
    }

    // ---- features: warp wid owns consecutive rows {8*wid .. 8*wid+7} ----
    #pragma unroll
    for (int j = 0; j < 8; ++j) {
        const int k   = 8 * wid + j;
        const int idx = sidx[k];
        const float4* __restrict__ src =
            reinterpret_cast<const float4*>(input + ((size_t)b * NN + (size_t)idx) * CC);
        float4* __restrict__ dst =
            reinterpret_cast<float4*>(out_feat + ((size_t)bm * KK + (size_t)k) * CC);
        dst[lane] = src[lane];
    }
}

extern "C" void kernel_launch(void* const* d_in, const int* in_sizes, int n_in,
                              void* d_out, int out_size)
{
    const float* input    = (const float*)d_in[0];  // [B,N,C]
    const float* points   = (const float*)d_in[1];  // [B,N,3]
    const float* next_pts = (const float*)d_in[2];  // [B,M,3]
    const int*   indices  = (const int*)  d_in[3];  // [B,M,K]

    float* out_pts  = (float*)d_out;                         // B*M*K*3
    float* out_feat = out_pts + (size_t)BB * MM * KK * 3;    // B*M*K*C

    const int grid = BB * MM;   // 32768 CTAs
    knn_gather_norm_v12_kernel<<<grid, 128>>>(input, points, next_pts, indices,
                                              out_pts, out_feat);
}

// round 14
// speedup vs baseline: 1.0293x; 1.0027x over previous
#include <cuda_runtime.h>
#include <cstdint>

// Problem constants (fixed by the reference)
#define BB 16
#define NN 8192
#define MM 2048
#define KK 32
#define CC 128

// out layout: [pts (B*M*K*3 floats)] ++ [features (B*M*K*C floats)]
//
// R12 (best: 94.2us kernel) with ONE change: uneven row split to balance
// warp 0's serial pts chain.
//   warp 0: pts (lane = neighbor k) + rows {0..4}   (5 rows)
//   warp 1: rows {5..13}                            (9 rows)
//   warp 2: rows {14..22}                           (9 rows)
//   warp 3: rows {23..31}                           (9 rows)
// 5 rows + ~600cyc pts chain ~= 9 rows, so all warps retire together and
// the CTA slot frees sooner. Strict per-row LDG.128 -> STG.128 interleave,
// consecutive rows per warp, 128 threads, 16 resident CTAs/SM.
__global__ __launch_bounds__(128, 16)
void knn_gather_norm_v13_kernel(const float* __restrict__ input,      // [B,N,C]
                                const float* __restrict__ points,     // [B,N,3]
                                const float* __restrict__ next_pts,   // [B,M,3]
                                const int*   __restrict__ indices,    // [B,M,K]
                                float* __restrict__ out_pts,          // [B,M,K,3]
                                float* __restrict__ out_feat)         // [B,M,K,C]
{
    const int bm = blockIdx.x;            // 0 .. B*M-1
    const int b  = bm / MM;

    __shared__ int sidx[KK];

    const int tid  = threadIdx.x;
    const int wid  = tid >> 5;
    const int lane = tid & 31;

    if (tid < KK) {
        sidx[tid] = indices[(size_t)bm * KK + tid];
    }
    __syncthreads();

    // ---- pts: warp 0, lane = neighbor k ----
    if (wid == 0) {
        const int k   = lane;
        const int idx = sidx[k];

        const float nx = __ldg(&next_pts[(size_t)bm * 3 + 0]);
        const float ny = __ldg(&next_pts[(size_t)bm * 3 + 1]);
        const float nz = __ldg(&next_pts[(size_t)bm * 3 + 2]);

        const float* p = points + ((size_t)b * NN + (size_t)idx) * 3;
        const float dx = __ldg(&p[0]) - nx;
        const float dy = __ldg(&p[1]) - ny;
        const float dz = __ldg(&p[2]) - nz;

        float mx = dx * dx + dy * dy + dz * dz;
        #pragma unroll
        for (int o = 16; o > 0; o >>= 1)
            mx = fmaxf(mx, __shfl_xor_sync(0xffffffffu, mx, o));

        float maxi = sqrtf(mx);
        if (maxi == 0.0f) maxi = 1.0f;
        const float inv = 1.0f / maxi;

        float* o = out_pts + ((size_t)bm * KK + (size_t)k) * 3;
        o[0] = dx * inv;
        o[1] = dy * inv;
        o[2] = dz * inv;
    }

    // ---- features: uneven consecutive split {5, 9, 9, 9} ----
    const int start = (wid == 0) ? 0 : 5 + (wid - 1) * 9;
    const int count = (wid == 0) ? 5 : 9;

    const float* __restrict__ in_b = input + (size_t)b * NN * CC;
    float4* __restrict__ of =
        reinterpret_cast<float4*>(out_feat + (size_t)bm * KK * CC);

    #pragma unroll
    for (int j = 0; j < 9; ++j) {
        if (j < count) {
            const int k   = start + j;
            const int idx = sidx[k];
            const float4 v =
                __ldg(reinterpret_cast<const float4*>(in_b + (size_t)idx * CC) + lane);
            of[(size_t)k * (CC / 4) + lane] = v;
        }
    }
}

extern "C" void kernel_launch(void* const* d_in, const int* in_sizes, int n_in,
                              void* d_out, int out_size)
{
    const float* input    = (const float*)d_in[0];  // [B,N,C]
    const float* points   = (const float*)d_in[1];  // [B,N,3]
    const float* next_pts = (const float*)d_in[2];  // [B,M,3]
    const int*   indices  = (const int*)  d_in[3];  // [B,M,K]

    float* out_pts  = (float*)d_out;                         // B*M*K*3
    float* out_feat = out_pts + (size_t)BB * MM * KK * 3;    // B*M*K*C

    const int grid = BB * MM;   // 32768 CTAs
    knn_gather_norm_v13_kernel<<<grid, 128>>>(input, points, next_pts, indices,
                                              out_pts, out_feat);
}